// round 11
// baseline (speedup 1.0000x reference)
#include <cuda_runtime.h>
#include <cuda_fp16.h>
#include <stdint.h>

#define THREADS 128
#define ROWS    32       // rows per block
#define PCOUNT  64       // predicates
#define PAD     33       // conflict-free row stride (ROWS+1)
#define C_MAX   128
#define NSPLIT  4        // clause quarters, one per warp
#define EROWS   128      // E-table: exp(+g_p) at row p, exp(-g_p) at row p+64

// Two descriptors per clause:
// g_to[c] = {e0|a0<<16, e1|a1<<16, e2|a2<<16, 0}   (element offsets)
//   e = (p + (sb?0:64))*PAD  into half E-table;  a = p*PAD into float acc
// g_tw[c] = {w0, w1, w2, 0}  pre-signed: sb ? +w : -w   (no sign ALU in main loop)
__device__ uint4  g_to[C_MAX];
__device__ float4 g_tw[C_MAX];

__device__ __forceinline__ float frcp(float x){ float y; asm("rcp.approx.f32 %0, %1;" : "=f"(y) : "f"(x)); return y; }
__device__ __forceinline__ float fex2(float x){ float y; asm("ex2.approx.f32 %0, %1;" : "=f"(y) : "f"(x)); return y; }

// literal_idx may physically be int32 (JAX x64-disabled) or int64; detect:
// int64 view of int32 data fuses two random indices -> out of [0,64) w.h.p.
__global__ void prep_kernel(const float* __restrict__ cw,
                            const void* __restrict__ litraw,
                            const int* __restrict__ sgn, int C)
{
    __shared__ int sh_is64;
    if (threadIdx.x == 0){
        const long long* v64 = (const long long*)litraw;
        int n = (C * 3) / 2;              // stays within int32-buffer bounds
        int ok = 1;
        for (int k = 0; k < n; k++){
            long long v = v64[k];
            if (v < 0 || v >= PCOUNT){ ok = 0; break; }
        }
        sh_is64 = ok;
    }
    __syncthreads();
    const int is64 = sh_is64;

    int c = blockIdx.x * blockDim.x + threadIdx.x;
    if (c >= C) return;
    float w = fminf(fmaxf(cw[c], 0.0f), 500.0f);     // clamp(0, 500)
    unsigned e[3], a[3]; float s[3];
    #pragma unroll
    for (int l = 0; l < 3; l++){
        int p = is64 ? (int)((const long long*)litraw)[c*3 + l]
                     :       ((const int*)litraw)[c*3 + l];
        int sb = sgn[c*3 + l];            // 1 -> +g half (+w), 0 -> -g half (-w)
        e[l] = (unsigned)((p + (sb ? 0 : PCOUNT)) * PAD);
        a[l] = (unsigned)(p * PAD);
        s[l] = sb ? w : -w;
    }
    g_to[c] = make_uint4(e[0] | (a[0] << 16), e[1] | (a[1] << 16),
                         e[2] | (a[2] << 16), 0u);
    g_tw[c] = make_float4(s[0], s[1], s[2], 0.0f);
}

__global__ void __launch_bounds__(THREADS)
main_kernel(const float* __restrict__ ga, float* __restrict__ out, int B)
{
    extern __shared__ char shb[];
    // layout: acc (33792B) | to (2048B) | tw (2048B) | E half (8448B) = 46336B
    // 5 blocks/SM: 5*46336 = 231680 <= 233472 (228KB)
    float*  __restrict__ A  = (float*)shb;
    uint4*  TO = (uint4*)(shb + NSPLIT*PCOUNT*PAD*4);
    float4* TW = (float4*)(TO + C_MAX);
    __half* __restrict__ Eh = (__half*)(TW + C_MAX);

    const int tid  = threadIdx.x;
    const int lane = tid & 31;
    const int wrp  = tid >> 5;
    const long long rowbase = (long long)blockIdx.x * ROWS;
    long long rem = (long long)B - rowbase;
    const int nrows = rem < ROWS ? (int)rem : ROWS;
    const size_t base = (size_t)rowbase * PCOUNT;

    if (tid < C_MAX){ TO[tid] = g_to[tid]; TW[tid] = g_tw[tid]; }

    // zero the 4 accumulator copies (vectorized)
    float4* A4 = (float4*)A;
    #pragma unroll
    for (int i = tid; i < NSPLIT*PCOUNT*PAD/4; i += THREADS)
        A4[i] = make_float4(0.f, 0.f, 0.f, 0.f);

    // Phase A: coalesced 32x64 tile load; build fp16 exp table (exp(+g), rcp).
    const float4* ga4 = (const float4*)(ga + base);
    const float L2E = 1.4426950408889634f;
    #pragma unroll
    for (int i = tid; i < ROWS*PCOUNT/4; i += THREADS){
        int o = i * 4, row = o >> 6, p = o & (PCOUNT-1);
        if (row < nrows){
            float4 g = ga4[i];
            float t;
            t = fex2(g.x*L2E); Eh[(p  )*PAD+row] = __float2half(t); Eh[(p+PCOUNT  )*PAD+row] = __float2half(frcp(t));
            t = fex2(g.y*L2E); Eh[(p+1)*PAD+row] = __float2half(t); Eh[(p+PCOUNT+1)*PAD+row] = __float2half(frcp(t));
            t = fex2(g.z*L2E); Eh[(p+2)*PAD+row] = __float2half(t); Eh[(p+PCOUNT+2)*PAD+row] = __float2half(frcp(t));
            t = fex2(g.w*L2E); Eh[(p+3)*PAD+row] = __float2half(t); Eh[(p+PCOUNT+3)*PAD+row] = __float2half(frcp(t));
        }
    }
    __syncthreads();

    // Phase B: warp w owns clause quarter [32w, 32w+32) and private acc copy.
    // Same structure as the 50.3us kernel minus the 9 sign-recovery ALU ops:
    // 2 broadcast LDS.128 for descriptors, 1 LOP3+SHF unpack per literal,
    // pre-signed weights. Gathers and acc RMWs conflict-free.
    {
        float* __restrict__ Aw = A + wrp * (PCOUNT*PAD);
        const int c0 = wrp * (C_MAX/NSPLIT);
        #pragma unroll 8
        for (int c = c0; c < c0 + C_MAX/NSPLIT; c++){
            uint4 t = TO[c]; float4 wv = TW[c];
            int e0 = (int)(t.x & 0xFFFF), a0 = (int)(t.x >> 16);
            int e1 = (int)(t.y & 0xFFFF), a1 = (int)(t.y >> 16);
            int e2 = (int)(t.z & 0xFFFF), a2 = (int)(t.z >> 16);
            float x0 = __half2float(Eh[e0 + lane]);
            float x1 = __half2float(Eh[e1 + lane]);
            float x2 = __half2float(Eh[e2 + lane]);
            float r  = frcp(x0 + x1 + x2);               // 1/sum(exp)
            Aw[a0 + lane] = fmaf(wv.x, x0*r, Aw[a0 + lane]);
            Aw[a1 + lane] = fmaf(wv.y, x1*r, Aw[a1 + lane]);
            Aw[a2 + lane] = fmaf(wv.z, x2*r, Aw[a2 + lane]);
        }
    }
    __syncthreads();

    // Reduce the 4 per-warp accumulator copies into copy 0 (vectorized).
    {
        const int n4 = PCOUNT*PAD/4;   // 528
        #pragma unroll
        for (int i = tid; i < n4; i += THREADS){
            float4 a = A4[i], b = A4[i + n4], c = A4[i + 2*n4], d = A4[i + 3*n4];
            a.x += b.x + c.x + d.x;
            a.y += b.y + c.y + d.y;
            a.z += b.z + c.z + d.z;
            a.w += b.w + c.w + d.w;
            A4[i] = a;
        }
    }
    __syncthreads();

    // Phase C: coalesced store of the 32x64 output tile (column reads are
    // conflict-free thanks to PAD=33).
    float4* out4 = (float4*)(out + base);
    #pragma unroll
    for (int i = tid; i < ROWS*PCOUNT/4; i += THREADS){
        int o = i*4, row = o >> 6, p = o & (PCOUNT-1);
        if (row < nrows){
            float4 v;
            v.x = A[(p  )*PAD + row];
            v.y = A[(p+1)*PAD + row];
            v.z = A[(p+2)*PAD + row];
            v.w = A[(p+3)*PAD + row];
            out4[i] = v;
        }
    }
}

extern "C" void kernel_launch(void* const* d_in, const int* in_sizes, int n_in,
                              void* d_out, int out_size)
{
    const float* ga  = (const float*)d_in[0];      // ground_atoms [B,64] f32
    const float* cw  = (const float*)d_in[1];      // clause_weights [C] f32
    const void*  lit = d_in[2];                    // literal_idx [C,3] i32-or-i64
    const int*   sgn = (const int*)d_in[3];        // sign_bits [C,3] i32
    float* out = (float*)d_out;

    int C = in_sizes[1];
    int B = in_sizes[0] / PCOUNT;
    int nblocks = (B + ROWS - 1) / ROWS;
    size_t smem = (size_t)NSPLIT*PCOUNT*PAD*4      // acc: 33792
                + C_MAX * (sizeof(uint4) + sizeof(float4))   // tables: 4096
                + (size_t)EROWS*PAD*2;             // E: 8448  => 46336 B -> 5 blocks/SM

    cudaFuncSetAttribute(main_kernel, cudaFuncAttributeMaxDynamicSharedMemorySize, (int)smem);
    prep_kernel<<<1, THREADS>>>(cw, lit, sgn, C);
    main_kernel<<<nblocks, THREADS, smem>>>(ga, out, B);
}

// round 12
// speedup vs baseline: 1.0694x; 1.0694x over previous
#include <cuda_runtime.h>
#include <cuda_fp16.h>
#include <stdint.h>

#define THREADS 128
#define ROWS    32       // rows per block
#define PCOUNT  64       // predicates
#define PAD     33       // conflict-free row stride (ROWS+1)
#define C_MAX   128
#define NSPLIT  4        // clause quarters, one per warp
#define EROWS   128      // E-table: exp(+g_p) at row p, exp(-g_p) at row p+64

// Clause descriptors (pre-signed weights, element offsets):
// g_to[c] = {e0|a0<<16, e1|a1<<16, e2|a2<<16, w0_bits}
//   e = (p + (sb?0:64))*PAD  into half E-table;  a = p*PAD into float acc
// g_tw[c] = {w1, w2}          w_l pre-signed: sb ? +w : -w
__device__ uint4  g_to[C_MAX];
__device__ float2 g_tw[C_MAX];

__device__ __forceinline__ float frcp(float x){ float y; asm("rcp.approx.f32 %0, %1;" : "=f"(y) : "f"(x)); return y; }
__device__ __forceinline__ float fex2(float x){ float y; asm("ex2.approx.f32 %0, %1;" : "=f"(y) : "f"(x)); return y; }

// literal_idx may physically be int32 (JAX x64-disabled) or int64; detect:
// int64 view of int32 data fuses two random indices -> out of [0,64) w.h.p.
__global__ void prep_kernel(const float* __restrict__ cw,
                            const void* __restrict__ litraw,
                            const int* __restrict__ sgn, int C)
{
    __shared__ int sh_is64;
    if (threadIdx.x == 0){
        const long long* v64 = (const long long*)litraw;
        int n = (C * 3) / 2;              // stays within int32-buffer bounds
        int ok = 1;
        for (int k = 0; k < n; k++){
            long long v = v64[k];
            if (v < 0 || v >= PCOUNT){ ok = 0; break; }
        }
        sh_is64 = ok;
    }
    __syncthreads();
    const int is64 = sh_is64;

    int c = blockIdx.x * blockDim.x + threadIdx.x;
    if (c >= C) return;
    float w = fminf(fmaxf(cw[c], 0.0f), 500.0f);     // clamp(0, 500)
    unsigned e[3], a[3]; float s[3];
    #pragma unroll
    for (int l = 0; l < 3; l++){
        int p = is64 ? (int)((const long long*)litraw)[c*3 + l]
                     :       ((const int*)litraw)[c*3 + l];
        int sb = sgn[c*3 + l];            // 1 -> +g half (+w), 0 -> -g half (-w)
        e[l] = (unsigned)((p + (sb ? 0 : PCOUNT)) * PAD);
        a[l] = (unsigned)(p * PAD);
        s[l] = sb ? w : -w;
    }
    g_to[c] = make_uint4(e[0] | (a[0] << 16), e[1] | (a[1] << 16),
                         e[2] | (a[2] << 16), __float_as_uint(s[0]));
    g_tw[c] = make_float2(s[1], s[2]);
}

__global__ void __launch_bounds__(THREADS)
main_kernel(const float* __restrict__ ga, float* __restrict__ out, int B)
{
    extern __shared__ char shb[];
    // layout: acc 33792 | TO 2048 | TW 1024 | E half 8448 = 45312 B
    // 1KB-granularity alloc: 45KB * 5 = 230400 <= 233472 -> 5 blocks/SM
    float*  __restrict__ A  = (float*)shb;
    uint4*  TO = (uint4*)(shb + NSPLIT*PCOUNT*PAD*4);
    float2* TW = (float2*)(TO + C_MAX);
    __half* __restrict__ Eh = (__half*)(TW + C_MAX);

    const int tid  = threadIdx.x;
    const int lane = tid & 31;
    const int wrp  = tid >> 5;
    const long long rowbase = (long long)blockIdx.x * ROWS;
    long long rem = (long long)B - rowbase;
    const int nrows = rem < ROWS ? (int)rem : ROWS;
    const size_t base = (size_t)rowbase * PCOUNT;

    if (tid < C_MAX){ TO[tid] = g_to[tid]; TW[tid] = g_tw[tid]; }

    // zero the 4 accumulator copies (vectorized)
    float4* A4 = (float4*)A;
    #pragma unroll
    for (int i = tid; i < NSPLIT*PCOUNT*PAD/4; i += THREADS)
        A4[i] = make_float4(0.f, 0.f, 0.f, 0.f);

    // Phase A: coalesced 32x64 tile load; build fp16 exp table (exp(+g), rcp).
    const float4* ga4 = (const float4*)(ga + base);
    const float L2E = 1.4426950408889634f;
    #pragma unroll
    for (int i = tid; i < ROWS*PCOUNT/4; i += THREADS){
        int o = i * 4, row = o >> 6, p = o & (PCOUNT-1);
        if (row < nrows){
            float4 g = ga4[i];
            float t;
            t = fex2(g.x*L2E); Eh[(p  )*PAD+row] = __float2half(t); Eh[(p+PCOUNT  )*PAD+row] = __float2half(frcp(t));
            t = fex2(g.y*L2E); Eh[(p+1)*PAD+row] = __float2half(t); Eh[(p+PCOUNT+1)*PAD+row] = __float2half(frcp(t));
            t = fex2(g.z*L2E); Eh[(p+2)*PAD+row] = __float2half(t); Eh[(p+PCOUNT+2)*PAD+row] = __float2half(frcp(t));
            t = fex2(g.w*L2E); Eh[(p+3)*PAD+row] = __float2half(t); Eh[(p+PCOUNT+3)*PAD+row] = __float2half(frcp(t));
        }
    }
    __syncthreads();

    // Phase B: warp w owns clause quarter [32w, 32w+32) and private acc copy.
    // Same inner loop as the ALU-lean R11 kernel: 1 LDS.128 + 1 LDS.64 broadcast
    // per clause, pre-signed weights, 1 unpack op per field. Gathers (LDS.U16
    // lane-consecutive) and acc RMWs conflict-free.
    {
        float* __restrict__ Aw = A + wrp * (PCOUNT*PAD);
        const int c0 = wrp * (C_MAX/NSPLIT);
        #pragma unroll 8
        for (int c = c0; c < c0 + C_MAX/NSPLIT; c++){
            uint4 t = TO[c]; float2 wv = TW[c];
            int e0 = (int)(t.x & 0xFFFF), a0 = (int)(t.x >> 16);
            int e1 = (int)(t.y & 0xFFFF), a1 = (int)(t.y >> 16);
            int e2 = (int)(t.z & 0xFFFF), a2 = (int)(t.z >> 16);
            float w0 = __uint_as_float(t.w);
            float x0 = __half2float(Eh[e0 + lane]);
            float x1 = __half2float(Eh[e1 + lane]);
            float x2 = __half2float(Eh[e2 + lane]);
            float r  = frcp(x0 + x1 + x2);               // 1/sum(exp)
            Aw[a0 + lane] = fmaf(w0,   x0*r, Aw[a0 + lane]);
            Aw[a1 + lane] = fmaf(wv.x, x1*r, Aw[a1 + lane]);
            Aw[a2 + lane] = fmaf(wv.y, x2*r, Aw[a2 + lane]);
        }
    }
    __syncthreads();

    // Reduce the 4 per-warp accumulator copies into copy 0 (vectorized).
    {
        const int n4 = PCOUNT*PAD/4;   // 528
        #pragma unroll
        for (int i = tid; i < n4; i += THREADS){
            float4 a = A4[i], b = A4[i + n4], c = A4[i + 2*n4], d = A4[i + 3*n4];
            a.x += b.x + c.x + d.x;
            a.y += b.y + c.y + d.y;
            a.z += b.z + c.z + d.z;
            a.w += b.w + c.w + d.w;
            A4[i] = a;
        }
    }
    __syncthreads();

    // Phase C: coalesced store of the 32x64 output tile (column reads are
    // conflict-free thanks to PAD=33).
    float4* out4 = (float4*)(out + base);
    #pragma unroll
    for (int i = tid; i < ROWS*PCOUNT/4; i += THREADS){
        int o = i*4, row = o >> 6, p = o & (PCOUNT-1);
        if (row < nrows){
            float4 v;
            v.x = A[(p  )*PAD + row];
            v.y = A[(p+1)*PAD + row];
            v.z = A[(p+2)*PAD + row];
            v.w = A[(p+3)*PAD + row];
            out4[i] = v;
        }
    }
}

extern "C" void kernel_launch(void* const* d_in, const int* in_sizes, int n_in,
                              void* d_out, int out_size)
{
    const float* ga  = (const float*)d_in[0];      // ground_atoms [B,64] f32
    const float* cw  = (const float*)d_in[1];      // clause_weights [C] f32
    const void*  lit = d_in[2];                    // literal_idx [C,3] i32-or-i64
    const int*   sgn = (const int*)d_in[3];        // sign_bits [C,3] i32
    float* out = (float*)d_out;

    int C = in_sizes[1];
    int B = in_sizes[0] / PCOUNT;
    int nblocks = (B + ROWS - 1) / ROWS;
    size_t smem = (size_t)NSPLIT*PCOUNT*PAD*4             // acc: 33792
                + C_MAX * (sizeof(uint4) + sizeof(float2))// tables: 3072
                + (size_t)EROWS*PAD*2;                    // E: 8448 => 45312 B

    cudaFuncSetAttribute(main_kernel, cudaFuncAttributeMaxDynamicSharedMemorySize, (int)smem);
    prep_kernel<<<1, THREADS>>>(cw, lit, sgn, C);
    main_kernel<<<nblocks, THREADS, smem>>>(ga, out, B);
}

// round 13
// speedup vs baseline: 1.1290x; 1.0558x over previous
#include <cuda_runtime.h>
#include <cuda_fp16.h>
#include <stdint.h>

#define THREADS 128
#define ROWS    32       // rows per block
#define PCOUNT  64       // predicates
#define PAD     33       // conflict-free row stride (ROWS+1)
#define C_MAX   128
#define NSPLIT  4        // clause quarters, one per warp
#define EROWS   128      // E-table: exp(+g_p) at row p, exp(-g_p) at row p+64
#define ACCSZ   (PCOUNT*PAD)     // halves per acc copy

// Clause descriptors:
// g_to[c] = {e0|a0<<16, e1|a1<<16, e2|a2<<16, h(w0)|h(w1)<<16}
//   e = (p + (sb?0:64))*PAD (half E-table elem offset), a = p*PAD (acc elem offset)
// g_tw[c] = h(w2)        weights pre-signed (sb ? +w : -w), stored as half
__device__ uint4          g_to[C_MAX];
__device__ unsigned short g_tw[C_MAX];

__device__ __forceinline__ float frcp(float x){ float y; asm("rcp.approx.f32 %0, %1;" : "=f"(y) : "f"(x)); return y; }
__device__ __forceinline__ float fex2(float x){ float y; asm("ex2.approx.f32 %0, %1;" : "=f"(y) : "f"(x)); return y; }
__device__ __forceinline__ float h2f(unsigned short u){ return __half2float(__ushort_as_half(u)); }
__device__ __forceinline__ unsigned short f2h(float f){ return __half_as_ushort(__float2half(f)); }

// literal_idx may physically be int32 (JAX x64-disabled) or int64; detect:
// int64 view of int32 data fuses two random indices -> out of [0,64) w.h.p.
__global__ void prep_kernel(const float* __restrict__ cw,
                            const void* __restrict__ litraw,
                            const int* __restrict__ sgn, int C)
{
    __shared__ int sh_is64;
    if (threadIdx.x == 0){
        const long long* v64 = (const long long*)litraw;
        int n = (C * 3) / 2;              // stays within int32-buffer bounds
        int ok = 1;
        for (int k = 0; k < n; k++){
            long long v = v64[k];
            if (v < 0 || v >= PCOUNT){ ok = 0; break; }
        }
        sh_is64 = ok;
    }
    __syncthreads();
    const int is64 = sh_is64;

    int c = blockIdx.x * blockDim.x + threadIdx.x;
    if (c >= C) return;
    float w = fminf(fmaxf(cw[c], 0.0f), 500.0f);     // clamp(0, 500)
    unsigned e[3], a[3]; float s[3];
    #pragma unroll
    for (int l = 0; l < 3; l++){
        int p = is64 ? (int)((const long long*)litraw)[c*3 + l]
                     :       ((const int*)litraw)[c*3 + l];
        int sb = sgn[c*3 + l];            // 1 -> +g half (+w), 0 -> -g half (-w)
        e[l] = (unsigned)((p + (sb ? 0 : PCOUNT)) * PAD);
        a[l] = (unsigned)(p * PAD);
        s[l] = sb ? w : -w;
    }
    g_to[c] = make_uint4(e[0] | (a[0] << 16), e[1] | (a[1] << 16),
                         e[2] | (a[2] << 16),
                         (unsigned)f2h(s[0]) | ((unsigned)f2h(s[1]) << 16));
    g_tw[c] = f2h(s[2]);
}

__global__ void __launch_bounds__(THREADS)
main_kernel(const float* __restrict__ ga, float* __restrict__ out, int B)
{
    extern __shared__ char shb[];
    // layout: acc half 16896 | E half 8448 | TO 2048 | TW 256 = 27648 B (27 KB)
    // -> 7-8 blocks/SM (vs 5 with fp32 accumulators)
    unsigned short* __restrict__ Au = (unsigned short*)shb;            // 4 acc copies
    __half*         __restrict__ Eh = (__half*)(shb + NSPLIT*ACCSZ*2);
    uint4*          TO = (uint4*)(shb + NSPLIT*ACCSZ*2 + EROWS*PAD*2);
    unsigned short* TW = (unsigned short*)(TO + C_MAX);

    const int tid  = threadIdx.x;
    const int lane = tid & 31;
    const int wrp  = tid >> 5;
    const long long rowbase = (long long)blockIdx.x * ROWS;
    long long rem = (long long)B - rowbase;
    const int nrows = rem < ROWS ? (int)rem : ROWS;
    const size_t base = (size_t)rowbase * PCOUNT;

    if (tid < C_MAX){ TO[tid] = g_to[tid]; TW[tid] = g_tw[tid]; }

    // zero the 4 half acc copies (vectorized: 16896 B = 1056 uint4)
    {
        uint4* Az = (uint4*)Au;
        #pragma unroll
        for (int i = tid; i < NSPLIT*ACCSZ*2/16; i += THREADS)
            Az[i] = make_uint4(0u, 0u, 0u, 0u);
    }

    // Phase A: coalesced 32x64 tile load; build fp16 exp table (exp(+g), rcp).
    const float4* ga4 = (const float4*)(ga + base);
    const float L2E = 1.4426950408889634f;
    #pragma unroll
    for (int i = tid; i < ROWS*PCOUNT/4; i += THREADS){
        int o = i * 4, row = o >> 6, p = o & (PCOUNT-1);
        if (row < nrows){
            float4 g = ga4[i];
            float t;
            t = fex2(g.x*L2E); Eh[(p  )*PAD+row] = __float2half(t); Eh[(p+PCOUNT  )*PAD+row] = __float2half(frcp(t));
            t = fex2(g.y*L2E); Eh[(p+1)*PAD+row] = __float2half(t); Eh[(p+PCOUNT+1)*PAD+row] = __float2half(frcp(t));
            t = fex2(g.z*L2E); Eh[(p+2)*PAD+row] = __float2half(t); Eh[(p+PCOUNT+2)*PAD+row] = __float2half(frcp(t));
            t = fex2(g.w*L2E); Eh[(p+3)*PAD+row] = __float2half(t); Eh[(p+PCOUNT+3)*PAD+row] = __float2half(frcp(t));
        }
    }
    __syncthreads();

    // Phase B: warp w owns clause quarter [32w, 32w+32) and a private half acc
    // copy. Math in fp32 (single rounding per store). Gathers (64B consecutive)
    // and acc RMWs conflict-free; descriptor loads are warp broadcasts.
    {
        unsigned short* __restrict__ Aw = Au + wrp * ACCSZ;
        const int c0 = wrp * (C_MAX/NSPLIT);
        #pragma unroll 8
        for (int c = c0; c < c0 + C_MAX/NSPLIT; c++){
            uint4 t = TO[c];
            int e0 = (int)(t.x & 0xFFFF), a0 = (int)(t.x >> 16);
            int e1 = (int)(t.y & 0xFFFF), a1 = (int)(t.y >> 16);
            int e2 = (int)(t.z & 0xFFFF), a2 = (int)(t.z >> 16);
            float w0 = h2f((unsigned short)(t.w & 0xFFFF));
            float w1 = h2f((unsigned short)(t.w >> 16));
            float w2 = h2f(TW[c]);
            float x0 = __half2float(Eh[e0 + lane]);
            float x1 = __half2float(Eh[e1 + lane]);
            float x2 = __half2float(Eh[e2 + lane]);
            float r  = frcp(x0 + x1 + x2);               // 1/sum(exp)
            int i0 = a0 + lane, i1 = a1 + lane, i2 = a2 + lane;
            Aw[i0] = f2h(fmaf(w0, x0*r, h2f(Aw[i0])));
            Aw[i1] = f2h(fmaf(w1, x1*r, h2f(Aw[i1])));
            Aw[i2] = f2h(fmaf(w2, x2*r, h2f(Aw[i2])));
        }
    }
    __syncthreads();

    // Phase C: reduce the 4 half copies in fp32 registers and store coalesced.
    // Reads are conflict-free: lane group k hits bank (2k + ...) distinct; the
    // two 16-lane row-groups share 4B words (broadcast-merged).
    float4* out4 = (float4*)(out + base);
    #pragma unroll
    for (int i = tid; i < ROWS*PCOUNT/4; i += THREADS){
        int o = i*4, row = o >> 6, p = o & (PCOUNT-1);
        if (row < nrows){
            float4 v;
            #pragma unroll
            for (int j = 0; j < 4; j++){
                int idx = (p + j)*PAD + row;
                float s = h2f(Au[idx])
                        + h2f(Au[idx +   ACCSZ])
                        + h2f(Au[idx + 2*ACCSZ])
                        + h2f(Au[idx + 3*ACCSZ]);
                ((float*)&v)[j] = s;
            }
            out4[i] = v;
        }
    }
}

extern "C" void kernel_launch(void* const* d_in, const int* in_sizes, int n_in,
                              void* d_out, int out_size)
{
    const float* ga  = (const float*)d_in[0];      // ground_atoms [B,64] f32
    const float* cw  = (const float*)d_in[1];      // clause_weights [C] f32
    const void*  lit = d_in[2];                    // literal_idx [C,3] i32-or-i64
    const int*   sgn = (const int*)d_in[3];        // sign_bits [C,3] i32
    float* out = (float*)d_out;

    int C = in_sizes[1];
    int B = in_sizes[0] / PCOUNT;
    int nblocks = (B + ROWS - 1) / ROWS;
    size_t smem = (size_t)NSPLIT*ACCSZ*2           // acc half: 16896
                + (size_t)EROWS*PAD*2              // E half:   8448
                + C_MAX * sizeof(uint4)            // TO:       2048
                + C_MAX * sizeof(unsigned short);  // TW:        256  => 27648 B

    cudaFuncSetAttribute(main_kernel, cudaFuncAttributeMaxDynamicSharedMemorySize, (int)smem);
    prep_kernel<<<1, THREADS>>>(cw, lit, sgn, C);
    main_kernel<<<nblocks, THREADS, smem>>>(ga, out, B);
}